// round 13
// baseline (speedup 1.0000x reference)
#include <cuda_runtime.h>
#include <math.h>

#define B_  32
#define C_  3
#define H_  480
#define W_  480
#define AH  30
#define AW  30
#define PAD 48          // int(0.1 * 480)

#define ROW_TILES 30
#define ROWS_PER_TILE 16
#define NBBOX (ROW_TILES * B_)      // 960 bbox tiles (blocks 0..959 contribute)

#define BROWS 30                    // rows per blend block
#define NGROUPS (H_ / BROWS)        // 16
#define NBLK (B_ * C_ * NGROUPS)    // 1536 blocks total
#define QW   (W_ / 4)               // 120 float4 pixels per row

// Encoded bbox accumulators, zero-init == "empty mask" defaults.
// [0]=H-minh, [1]=maxh+1, [2]=W-minw, [3]=maxw+1; atomicMax -> replay-idempotent.
__device__ int g_enc[B_][4];
// Monotone per-batch completion counters: +ROW_TILES per launch. Never reset.
__device__ int g_cnt[B_];
// Monotone launch ticket: epoch = ticket / NBLK. Never reset.
__device__ unsigned long long g_ticket;

// ---------------------------------------------------------------------------
__global__ void __launch_bounds__(128) fused_kernel(const float* __restrict__ images,
                                                    const float* __restrict__ atten,
                                                    float* __restrict__ out) {
    __shared__ union {
        struct {
            float att[AH * AW];
            float wmax[4];
            int   minh, maxh, minw, maxw;
        } A;
        __align__(16) float row[2][484];
    } sm;
    __shared__ int s_epoch;

    const int bid = blockIdx.x;
    const int tid = threadIdx.x;

    // launch epoch from monotone ticket (replay-safe, no resets)
    if (tid == 0) {
        unsigned long long t = atomicAdd(&g_ticket, 1ULL);
        s_epoch = (int)(t / (unsigned long long)NBLK);
    }

    // ================= Phase 1: bbox tile (blocks 0..959) =================
    if (bid < NBBOX) {
        const int bb   = bid / ROW_TILES;
        const int tile = bid - bb * ROW_TILES;

        const float* a = atten + bb * (AH * AW);
        float m = -1e30f;
        for (int i = tid; i < AH * AW; i += 128) {
            float v = a[i];
            sm.A.att[i] = v;
            m = fmaxf(m, v);
        }
#pragma unroll
        for (int s = 16; s > 0; s >>= 1)
            m = fmaxf(m, __shfl_xor_sync(0xffffffffu, m, s));
        if ((tid & 31) == 0) sm.A.wmax[tid >> 5] = m;
        if (tid == 0) { sm.A.minh = H_; sm.A.maxh = -1; sm.A.minw = W_; sm.A.maxw = -1; }
        __syncthreads();
        const float theta = 0.5f * fmaxf(fmaxf(sm.A.wmax[0], sm.A.wmax[1]),
                                         fmaxf(sm.A.wmax[2], sm.A.wmax[3]));

        int minh = H_, maxh = -1, minw = W_, maxw = -1;
        const int h_start = tile * ROWS_PER_TILE;
#pragma unroll 1
        for (int h = h_start; h < h_start + ROWS_PER_TILE; ++h) {
            float sy = (h + 0.5f) * 0.0625f - 0.5f;
            sy = fminf(fmaxf(sy, 0.0f), (float)(AH - 1));
            const int   y0 = (int)sy;
            const float wy = sy - (float)y0;
            const int   y1 = min(y0 + 1, AH - 1);
            const float* r0p = sm.A.att + y0 * AW;
            const float* r1p = sm.A.att + y1 * AW;

#pragma unroll 1
            for (int w = tid; w < W_; w += 128) {
                float sx = (w + 0.5f) * 0.0625f - 0.5f;
                sx = fminf(fmaxf(sx, 0.0f), (float)(AW - 1));
                const int   x0 = (int)sx;
                const float wx = sx - (float)x0;
                const int   x1 = min(x0 + 1, AW - 1);

                const float ra = r0p[x0] * (1.0f - wy) + r1p[x0] * wy;
                const float rb = r0p[x1] * (1.0f - wy) + r1p[x1] * wy;
                const float up = ra * (1.0f - wx) + rb * wx;

                if (up >= theta) {
                    minh = min(minh, h); maxh = max(maxh, h);
                    minw = min(minw, w); maxw = max(maxw, w);
                }
            }
        }

        atomicMin(&sm.A.minh, minh); atomicMax(&sm.A.maxh, maxh);
        atomicMin(&sm.A.minw, minw); atomicMax(&sm.A.maxw, maxw);
        __syncthreads();

        if (tid == 0) {
            if (sm.A.maxh >= 0) {
                atomicMax(&g_enc[bb][0], H_ - sm.A.minh);
                atomicMax(&g_enc[bb][1], sm.A.maxh + 1);
                atomicMax(&g_enc[bb][2], W_ - sm.A.minw);
                atomicMax(&g_enc[bb][3], sm.A.maxw + 1);
            }
            __threadfence();
            atomicAdd(&g_cnt[bb], 1);       // publish this tile's completion
        }
    }

    // ================= Dependency wait (data flag, not a barrier) ============
    const int b   = bid / (C_ * NGROUPS);
    const int rem = bid - b * (C_ * NGROUPS);
    const int c   = rem / NGROUPS;
    const int y_base = (rem - c * NGROUPS) * BROWS;

    if (tid == 0) {
        const int target = (s_epoch + 1) * ROW_TILES;   // 30 tiles this launch
        const volatile int* p = &g_cnt[b];
        while (*p < target) { __nanosleep(64); }
    }
    __syncthreads();                // also fences smem union reuse
    __threadfence();

    // ================= Phase 2: blend (R11 body, 30 rows) ===================
    // decode + pad + clamp bbox
    const int minh = H_ - g_enc[b][0];
    const int maxh = g_enc[b][1] - 1;
    const int minw = W_ - g_enc[b][2];
    const int maxw = g_enc[b][3] - 1;
    const int h0 = max(minh - PAD, 0);
    const int h1 = min(maxh + PAD, H_);
    const int w0 = max(minw - PAD, 0);
    const int w1 = min(maxw + PAD, W_);

    const int   crop_h = h1 - h0;
    const int   crop_w = w1 - w0;
    const float chf = (float)crop_h;
    const float cwf = (float)crop_w;
    const float sy_scale = chf * (1.0f / (float)H_);
    const float sx_scale = cwf * (1.0f / (float)W_);

    const int w0a = w0 & ~3;
    const int off = w0 - w0a;
    const int nq  = ((w1 - w0a) + 3) >> 2;      // <= 121

    int   fxa[4], fxb[4];
    float wxv[4];
    const int x_base = tid * 4;
    if (tid < QW) {
#pragma unroll
        for (int k = 0; k < 4; ++k) {
            float sx = ((float)(x_base + k) + 0.5f) * sx_scale - 0.5f;
            sx = fminf(fmaxf(sx, 0.0f), cwf - 1.0f);
            const int fx0 = (int)sx;
            wxv[k] = sx - (float)fx0;
            fxa[k] = off + fx0;
            fxb[k] = off + min(fx0 + 1, crop_w - 1);
        }
    }

    const float* __restrict__ imgc = images + ((size_t)(b * C_ + c)) * (H_ * W_);
    float* __restrict__ outc       = out    + ((size_t)(b * C_ + c)) * (H_ * W_);

#pragma unroll 1
    for (int r = 0; r < BROWS; ++r) {
        const int y = y_base + r;
        float* buf = sm.row[r & 1];

        float sy = ((float)y + 0.5f) * sy_scale - 0.5f;
        sy = fminf(fmaxf(sy, 0.0f), chf - 1.0f);
        const int   fy0  = (int)sy;
        const float wy   = sy - (float)fy0;
        const float omwy = 1.0f - wy;
        const size_t r0  = (size_t)(h0 + fy0) * W_ + w0a;
        const size_t r1  = (size_t)(h0 + min(fy0 + 1, crop_h - 1)) * W_ + w0a;

        if (tid < nq) {
            const float4 a0 = *reinterpret_cast<const float4*>(imgc + r0 + 4 * tid);
            const float4 a1 = *reinterpret_cast<const float4*>(imgc + r1 + 4 * tid);
            float4 v;
            v.x = a0.x * omwy + a1.x * wy;
            v.y = a0.y * omwy + a1.y * wy;
            v.z = a0.z * omwy + a1.z * wy;
            v.w = a0.w * omwy + a1.w * wy;
            *reinterpret_cast<float4*>(&buf[4 * tid]) = v;
        }

        float4 idv = make_float4(0.f, 0.f, 0.f, 0.f);
        if (tid < QW)
            idv = *reinterpret_cast<const float4*>(imgc + (size_t)y * W_ + x_base);

        __syncthreads();

        if (tid < QW) {
            float4 o;
            o.x = idv.x * 0.6f + 0.4f * (buf[fxa[0]] * (1.0f - wxv[0]) + buf[fxb[0]] * wxv[0]);
            o.y = idv.y * 0.6f + 0.4f * (buf[fxa[1]] * (1.0f - wxv[1]) + buf[fxb[1]] * wxv[1]);
            o.z = idv.z * 0.6f + 0.4f * (buf[fxa[2]] * (1.0f - wxv[2]) + buf[fxb[2]] * wxv[2]);
            o.w = idv.w * 0.6f + 0.4f * (buf[fxa[3]] * (1.0f - wxv[3]) + buf[fxb[3]] * wxv[3]);
            *reinterpret_cast<float4*>(outc + (size_t)y * W_ + x_base) = o;
        }
    }
}

// ---------------------------------------------------------------------------
extern "C" void kernel_launch(void* const* d_in, const int* in_sizes, int n_in,
                              void* d_out, int out_size) {
    const float* images = (const float*)d_in[0];
    const float* atten  = (const float*)d_in[1];
    float* out = (float*)d_out;

    fused_kernel<<<NBLK, 128>>>(images, atten, out);
}

// round 14
// speedup vs baseline: 1.3721x; 1.3721x over previous
#include <cuda_runtime.h>
#include <math.h>

#define B_  32
#define C_  3
#define H_  480
#define W_  480
#define AH  30
#define AW  30
#define PAD 48          // int(0.1 * 480)

#define ROW_TILES 60            // 8 rows per bbox tile -> 1920 blocks
#define ROWS_PER_TILE 8

#define BROWS 60                // rows per blend block -> 8 groups -> 768 blocks
#define NGROUPS (H_ / BROWS)    // 8
#define QW   (W_ / 4)           // 120 float4 pixels per row

// Encoded bbox accumulators, zero-init == "empty mask" defaults.
// [0] = H - minh, [1] = maxh + 1, [2] = W - minw, [3] = maxw + 1.
// atomicMax-combined -> idempotent across graph replays.
__device__ int g_enc[B_][4];

// ---------------------------------------------------------------------------
// Kernel A: theta + mask tile + bbox atomics. grid=(ROW_TILES, B_), 256 thr.
// ---------------------------------------------------------------------------
__global__ void __launch_bounds__(256) bbox_kernel(const float* __restrict__ atten) {
    const int b    = blockIdx.y;
    const int tile = blockIdx.x;
    const int tid  = threadIdx.x;

    __shared__ float s_att[AH * AW];
    __shared__ float s_wmax[8];
    __shared__ int s_minh, s_maxh, s_minw, s_maxw;

    const float* a = atten + b * (AH * AW);
    float m = -1e30f;
    for (int i = tid; i < AH * AW; i += 256) {
        float v = a[i];
        s_att[i] = v;
        m = fmaxf(m, v);
    }
#pragma unroll
    for (int s = 16; s > 0; s >>= 1)
        m = fmaxf(m, __shfl_xor_sync(0xffffffffu, m, s));
    if ((tid & 31) == 0) s_wmax[tid >> 5] = m;
    if (tid == 0) { s_minh = H_; s_maxh = -1; s_minw = W_; s_maxw = -1; }
    __syncthreads();
    float mm = fmaxf(fmaxf(fmaxf(s_wmax[0], s_wmax[1]), fmaxf(s_wmax[2], s_wmax[3])),
                     fmaxf(fmaxf(s_wmax[4], s_wmax[5]), fmaxf(s_wmax[6], s_wmax[7])));
    const float theta = 0.5f * mm;

    int minh = H_, maxh = -1, minw = W_, maxw = -1;

    const int h_start = tile * ROWS_PER_TILE;
#pragma unroll 1
    for (int h = h_start; h < h_start + ROWS_PER_TILE; ++h) {
        float sy = (h + 0.5f) * 0.0625f - 0.5f;
        sy = fminf(fmaxf(sy, 0.0f), (float)(AH - 1));
        const int   y0 = (int)sy;
        const float wy = sy - (float)y0;
        const int   y1 = min(y0 + 1, AH - 1);
        const float* r0p = s_att + y0 * AW;
        const float* r1p = s_att + y1 * AW;

#pragma unroll 1
        for (int w = tid; w < W_; w += 256) {
            float sx = (w + 0.5f) * 0.0625f - 0.5f;
            sx = fminf(fmaxf(sx, 0.0f), (float)(AW - 1));
            const int   x0 = (int)sx;
            const float wx = sx - (float)x0;
            const int   x1 = min(x0 + 1, AW - 1);

            const float ra = r0p[x0] * (1.0f - wy) + r1p[x0] * wy;
            const float rb = r0p[x1] * (1.0f - wy) + r1p[x1] * wy;
            const float up = ra * (1.0f - wx) + rb * wx;

            if (up >= theta) {
                minh = min(minh, h); maxh = max(maxh, h);
                minw = min(minw, w); maxw = max(maxw, w);
            }
        }
    }

    atomicMin(&s_minh, minh); atomicMax(&s_maxh, maxh);
    atomicMin(&s_minw, minw); atomicMax(&s_maxw, maxw);
    __syncthreads();

    if (tid == 0 && s_maxh >= 0) {
        atomicMax(&g_enc[b][0], H_ - s_minh);
        atomicMax(&g_enc[b][1], s_maxh + 1);
        atomicMax(&g_enc[b][2], W_ - s_minw);
        atomicMax(&g_enc[b][3], s_maxw + 1);
    }

    asm volatile("griddepcontrol.launch_dependents;" ::: "memory");
}

// ---------------------------------------------------------------------------
// Kernel B: fused crop-resize + mixup blend, 256 threads = 2 rows per barrier.
// Warp-half 0 (tid 0..127) handles even rows, half 1 (tid 128..255) odd rows.
// One block per (b, c, 60-row group); 768 blocks = single wave.
// ---------------------------------------------------------------------------
__global__ void __launch_bounds__(256) blend_kernel(const float* __restrict__ images,
                                                    float* __restrict__ out) {
    const int blk = blockIdx.x;                 // (b, c, rowgroup)
    const int b   = blk / (C_ * NGROUPS);
    const int rem = blk - b * (C_ * NGROUPS);
    const int c   = rem / NGROUPS;
    const int y_base = (rem - c * NGROUPS) * BROWS;
    const int tid  = threadIdx.x;
    const int half = tid >> 7;                  // 0 or 1
    const int htid = tid & 127;                 // lane within half

    __shared__ __align__(16) float s_row[2][484];   // one buffer per half

    asm volatile("griddepcontrol.wait;" ::: "memory");

    // decode + pad + clamp bbox (once per block)
    const int minh = H_ - g_enc[b][0];
    const int maxh = g_enc[b][1] - 1;
    const int minw = W_ - g_enc[b][2];
    const int maxw = g_enc[b][3] - 1;
    const int h0 = max(minh - PAD, 0);
    const int h1 = min(maxh + PAD, H_);
    const int w0 = max(minw - PAD, 0);
    const int w1 = min(maxw + PAD, W_);

    const int   crop_h = h1 - h0;
    const int   crop_w = w1 - w0;
    const float chf = (float)crop_h;
    const float cwf = (float)crop_w;
    const float sy_scale = chf * (1.0f / (float)H_);
    const float sx_scale = cwf * (1.0f / (float)W_);

    const int w0a = w0 & ~3;                    // float4-aligned window start
    const int off = w0 - w0a;
    const int nq  = ((w1 - w0a) + 3) >> 2;      // quads to fill (<= 121)

    // per-thread x-mapping, computed ONCE (same for both halves)
    int   fxa[4], fxb[4];
    float wxv[4];
    const int x_base = htid * 4;
    if (htid < QW) {
#pragma unroll
        for (int k = 0; k < 4; ++k) {
            float sx = ((float)(x_base + k) + 0.5f) * sx_scale - 0.5f;
            sx = fminf(fmaxf(sx, 0.0f), cwf - 1.0f);
            const int fx0 = (int)sx;
            wxv[k] = sx - (float)fx0;
            fxa[k] = off + fx0;
            fxb[k] = off + min(fx0 + 1, crop_w - 1);
        }
    }

    const float* __restrict__ imgc = images + ((size_t)(b * C_ + c)) * (H_ * W_);
    float* __restrict__ outc       = out    + ((size_t)(b * C_ + c)) * (H_ * W_);
    float* __restrict__ buf        = s_row[half];

#pragma unroll 1
    for (int r = 0; r < BROWS / 2; ++r) {
        const int y = y_base + 2 * r + half;    // half 0 -> even, half 1 -> odd

        // per-half y mapping
        float sy = ((float)y + 0.5f) * sy_scale - 0.5f;
        sy = fminf(fmaxf(sy, 0.0f), chf - 1.0f);
        const int   fy0  = (int)sy;
        const float wy   = sy - (float)fy0;
        const float omwy = 1.0f - wy;
        const size_t r0  = (size_t)(h0 + fy0) * W_ + w0a;
        const size_t r1  = (size_t)(h0 + min(fy0 + 1, crop_h - 1)) * W_ + w0a;

        // cooperative vectorized y-lerp fill (each half fills its own buffer)
        if (htid < nq) {
            const float4 a0 = *reinterpret_cast<const float4*>(imgc + r0 + 4 * htid);
            const float4 a1 = *reinterpret_cast<const float4*>(imgc + r1 + 4 * htid);
            float4 v;
            v.x = a0.x * omwy + a1.x * wy;
            v.y = a0.y * omwy + a1.y * wy;
            v.z = a0.z * omwy + a1.z * wy;
            v.w = a0.w * omwy + a1.w * wy;
            *reinterpret_cast<float4*>(&buf[4 * htid]) = v;
        }

        // identity pixels (coalesced float4)
        float4 idv = make_float4(0.f, 0.f, 0.f, 0.f);
        if (htid < QW)
            idv = *reinterpret_cast<const float4*>(imgc + (size_t)y * W_ + x_base);

        __syncthreads();        // ONE barrier for TWO rows

        if (htid < QW) {
            float4 o;
            o.x = idv.x * 0.6f + 0.4f * (buf[fxa[0]] * (1.0f - wxv[0]) + buf[fxb[0]] * wxv[0]);
            o.y = idv.y * 0.6f + 0.4f * (buf[fxa[1]] * (1.0f - wxv[1]) + buf[fxb[1]] * wxv[1]);
            o.z = idv.z * 0.6f + 0.4f * (buf[fxa[2]] * (1.0f - wxv[2]) + buf[fxb[2]] * wxv[2]);
            o.w = idv.w * 0.6f + 0.4f * (buf[fxa[3]] * (1.0f - wxv[3]) + buf[fxb[3]] * wxv[3]);
            *reinterpret_cast<float4*>(outc + (size_t)y * W_ + x_base) = o;
        }

        __syncthreads();        // protect buffers before next fill
    }
}

// ---------------------------------------------------------------------------
extern "C" void kernel_launch(void* const* d_in, const int* in_sizes, int n_in,
                              void* d_out, int out_size) {
    const float* images = (const float*)d_in[0];
    const float* atten  = (const float*)d_in[1];
    float* out = (float*)d_out;

    bbox_kernel<<<dim3(ROW_TILES, B_), 256>>>(atten);

    cudaLaunchConfig_t cfg = {};
    cfg.gridDim  = dim3(B_ * C_ * NGROUPS);     // 768 blocks x 256 thr, 1 wave
    cfg.blockDim = dim3(256);
    cfg.dynamicSmemBytes = 0;
    cfg.stream = 0;
    cudaLaunchAttribute attrs[1];
    attrs[0].id = cudaLaunchAttributeProgrammaticStreamSerialization;
    attrs[0].val.programmaticStreamSerializationAllowed = 1;
    cfg.attrs = attrs;
    cfg.numAttrs = 1;
    cudaLaunchKernelEx(&cfg, blend_kernel, images, out);
}